// round 1
// baseline (speedup 1.0000x reference)
#include <cuda_runtime.h>
#include <math.h>

// Problem constants (fixed shapes from the reference)
#define B 128
#define C 512
#define HW 1024            // 32*32
#define E 16
#define KTOP 2
#define NOISE_STD_INV 16.0f   // 1 / (1/E) = E
#define TAU 1.0f
#define EPS 1e-8f

// Scratch (no allocations allowed in kernel_launch)
__device__ float g_pooled[B * C];   // 256 KB
__device__ float g_logits[B * E];   // 8 KB

// ---------------------------------------------------------------------------
// Kernel 1: adaptive avg pool.  One warp per (b,c) row of 1024 contiguous f32.
// ---------------------------------------------------------------------------
__global__ void pool_kernel(const float* __restrict__ x) {
    int gwarp = (blockIdx.x * blockDim.x + threadIdx.x) >> 5;
    int lane  = threadIdx.x & 31;
    if (gwarp >= B * C) return;

    const float4* row = reinterpret_cast<const float4*>(x + (size_t)gwarp * HW);
    float s = 0.0f;
#pragma unroll
    for (int j = 0; j < 8; ++j) {
        float4 v = __ldg(&row[lane + 32 * j]);
        s += (v.x + v.y) + (v.z + v.w);
    }
#pragma unroll
    for (int o = 16; o; o >>= 1) s += __shfl_xor_sync(0xffffffffu, s, o);
    if (lane == 0) g_pooled[gwarp] = s * (1.0f / (float)HW);
}

// ---------------------------------------------------------------------------
// Kernel 2: logits = pooled @ W_gate^T.  One block per b, one warp per expert.
// ---------------------------------------------------------------------------
__global__ void gate_gemm_kernel(const float* __restrict__ Wg) {
    __shared__ float sp[C];
    int b = blockIdx.x;
    sp[threadIdx.x] = g_pooled[b * C + threadIdx.x];
    __syncthreads();

    int e    = threadIdx.x >> 5;   // 0..15
    int lane = threadIdx.x & 31;
    const float* wrow = Wg + e * C;
    float s = 0.0f;
#pragma unroll
    for (int j = 0; j < C / 32; ++j)
        s = fmaf(sp[lane + 32 * j], __ldg(&wrow[lane + 32 * j]), s);
#pragma unroll
    for (int o = 16; o; o >>= 1) s += __shfl_xor_sync(0xffffffffu, s, o);
    if (lane == 0) g_logits[b * E + e] = s;
}

// ---------------------------------------------------------------------------
// Kernel 3: softmaxes, top-2, gates scatter, aux losses.  Single block.
// Deterministic reductions (no float atomics) -> bitwise stable per replay.
// ---------------------------------------------------------------------------
__global__ void finalize_kernel(const float* __restrict__ complexity,
                                const float* __restrict__ noise,
                                float* __restrict__ out) {
    __shared__ float sm_clean[B][E];   // clean softmax probs
    __shared__ float sm_p[B][E];       // load-balance p values
    __shared__ float sh_imp[E];
    __shared__ float sh_pm[E];

    int b = threadIdx.x;
    if (b < B) {
        float l[E], n[E];
#pragma unroll
        for (int e = 0; e < E; ++e) {
            l[e] = g_logits[b * E + e];
            n[e] = l[e] + noise[b * E + e];
        }
        // clean softmax
        {
            float mx = l[0];
#pragma unroll
            for (int e = 1; e < E; ++e) mx = fmaxf(mx, l[e]);
            float ssum = 0.0f, t[E];
#pragma unroll
            for (int e = 0; e < E; ++e) { t[e] = expf(l[e] - mx); ssum += t[e]; }
            float inv = 1.0f / ssum;
#pragma unroll
            for (int e = 0; e < E; ++e) sm_clean[b][e] = t[e] * inv;
        }
        // noisy softmax
        float g[E];
        {
            float mx = n[0];
#pragma unroll
            for (int e = 1; e < E; ++e) mx = fmaxf(mx, n[e]);
            float ssum = 0.0f;
#pragma unroll
            for (int e = 0; e < E; ++e) { g[e] = expf(n[e] - mx); ssum += g[e]; }
            float inv = 1.0f / ssum;
#pragma unroll
            for (int e = 0; e < E; ++e) g[e] *= inv;
        }
        // top-2 of g (== top-2 of n, softmax is monotone). Strict > => lowest
        // index wins ties, matching jax.lax.top_k.
        int i1 = 0;
#pragma unroll
        for (int e = 1; e < E; ++e) if (g[e] > g[i1]) i1 = e;
        int i2 = (i1 == 0) ? 1 : 0;
#pragma unroll
        for (int e = 0; e < E; ++e) if (e != i1 && g[e] > g[i2]) i2 = e;
        float v1 = g[i1], v2 = g[i2];
        float thr = n[i2];   // value of 2nd-largest noisy logit

        // gates row + topk outputs
#pragma unroll
        for (int e = 0; e < E; ++e)
            out[b * E + e] = (e == i1) ? v1 : ((e == i2) ? v2 : 0.0f);
        out[B * E + b * KTOP + 0]            = (float)i1;
        out[B * E + b * KTOP + 1]            = (float)i2;
        out[B * E + B * KTOP + b * KTOP + 0] = v1;
        out[B * E + B * KTOP + b * KTOP + 1] = v2;

        // p[e] = 1 - Phi((thr - l[e]) / sigma) = 0.5 * erfc(z / sqrt(2))
#pragma unroll
        for (int e = 0; e < E; ++e) {
            float z = (thr - l[e]) * NOISE_STD_INV;
            sm_p[b][e] = 0.5f * erfcf(z * 0.70710678118654752f);
        }
    }
    __syncthreads();

    if (threadIdx.x < E) {
        int e = threadIdx.x;
        float si = 0.0f, sp = 0.0f;
        for (int bb = 0; bb < B; ++bb) { si += sm_clean[bb][e]; sp += sm_p[bb][e]; }
        sh_imp[e] = si * (complexity[e] * TAU);
        sh_pm[e]  = sp * (1.0f / (float)B);
    }
    __syncthreads();

    if (threadIdx.x == 0) {
        float mi = 0.0f, mp = 0.0f;
#pragma unroll
        for (int e = 0; e < E; ++e) { mi += sh_imp[e]; mp += sh_pm[e]; }
        mi *= (1.0f / (float)E);
        mp *= (1.0f / (float)E);
        float vi = 0.0f, vp = 0.0f;
#pragma unroll
        for (int e = 0; e < E; ++e) {
            float di = sh_imp[e] - mi; vi += di * di;
            float dp = sh_pm[e]  - mp; vp += dp * dp;
        }
        vi *= (1.0f / (float)(E - 1));   // ddof=1
        vp *= (1.0f / (float)(E - 1));
        float cvi = sqrtf(vi) / (mi + EPS);
        float cvp = sqrtf(vp) / (mp + EPS);
        out[B * E + 2 * B * KTOP] = 0.5f * (cvi * cvi) + 0.5f * (cvp * cvp);
    }
}

// ---------------------------------------------------------------------------
extern "C" void kernel_launch(void* const* d_in, const int* in_sizes, int n_in,
                              void* d_out, int out_size) {
    const float* x          = (const float*)d_in[0];
    const float* W_gate     = (const float*)d_in[1];
    const float* complexity = (const float*)d_in[2];
    const float* noise      = (const float*)d_in[3];
    float* out = (float*)d_out;

    // 1 warp per (b,c) row; 8 warps per block
    int rows = B * C;                       // 65536
    int blocks = rows / 8;                  // 8192
    pool_kernel<<<blocks, 256>>>(x);
    gate_gemm_kernel<<<B, C>>>(W_gate);
    finalize_kernel<<<1, 128>>>(complexity, noise, out);
}